// round 11
// baseline (speedup 1.0000x reference)
#include <cuda_runtime.h>
#include <cstdint>

// out = relu( GroupNorm32( Wv @ feat + bv, gn_v_g, gn_v_b ) )
// (softmax-weighted sum in the reference is identity: v is constant along the
//  softmax axis and softmax rows sum to 1).
//
// feat [2,128,512], Wv [128,128], out [2,128,512].
//
// RETILED vs R8/R9: CTA = (batch, 8-point slice) computing ALL 128 channels.
//   grid 128 = 2 batches x 64 slices, 256 threads (pt = t&7, chquad = t>>3).
//   Per-CTA global reads: 4KB feat slice + 64KB W  (vs 256KB feat before:
//   kills the 32x feat L2 amplification and the L1tex queue pressure).
// W staged in smem in two 32KB halves (half 2 prefetched to registers during
// pass 0).  XOR swizzle (ck ^ cq) makes W LDS.128 conflict-free & aligned.
// GN stats: per-CTA per-group partials -> global scratch -> ticket-based
// grid-wide barrier (monotonic counter, graph-replay safe, all 128 CTAs
// co-resident so no deadlock) -> every CTA recombines the 64 slice partials
// in a FIXED order (deterministic) -> normalize from registers.

#define C_CH   128
#define NPT    512
#define EPS_GN 1e-5f
#define NT     256
#define FSTR   132   // fsm row stride (floats): bank offset 4 per pt
#define WSTR   68    // wsm row stride (floats): 64 cols + 4 pad

__device__ float2   g_part[2][64][32];   // [b][slice][group] {sum, sumsq}
__device__ unsigned g_ctr;               // zero-init; +128 per launch

__global__ __launch_bounds__(NT, 1)
void fused_v_gn_relu_kernel(const float* __restrict__ feat,
                            const float* __restrict__ Wv,
                            const float* __restrict__ bv,
                            const float* __restrict__ gamma,
                            const float* __restrict__ beta,
                            float* __restrict__ out) {
    const int bid   = blockIdx.x;
    const int slice = bid & 63;
    const int b     = bid >> 6;
    const int p0    = slice * 8;
    const int t     = threadIdx.x;   // 0..255
    const int pt    = t & 7;         // point within slice
    const int cq    = t >> 3;        // channel quad 0..31 (== GN group)

    __shared__ __align__(16) float wsm[C_CH * WSTR];   // 34.8KB
    __shared__ __align__(16) float fsm[8 * FSTR];      // 4.2KB
    __shared__ float gsm[C_CH], bsm[C_CH], bvs[C_CH];
    __shared__ float2 stat_s[32];

    // ---- Stage feat slice: fsm[pt][cc] ----
    {
        const int cc = t >> 1, h = t & 1;
        const float4 f = *(const float4*)(feat + (size_t)b * C_CH * NPT
                                          + cc * NPT + p0 + 4 * h);
        fsm[(4 * h + 0) * FSTR + cc] = f.x;
        fsm[(4 * h + 1) * FSTR + cc] = f.y;
        fsm[(4 * h + 2) * FSTR + cc] = f.z;
        fsm[(4 * h + 3) * FSTR + cc] = f.w;
    }
    if (t < C_CH) {
        gsm[t] = gamma[t];
        bsm[t] = beta[t];
        bvs[t] = bv[t];
    }
    // ---- Stage W half 0 (cc 0..63), swizzled: slot = c4 ^ (ch>>2 & 3) ----
    #pragma unroll
    for (int k = 0; k < 8; k++) {
        const int flat = t + NT * k;          // 0..2047 float4 tiles
        const int ch = flat >> 4, c4 = flat & 15;
        const float4 w = *(const float4*)(Wv + ch * C_CH + 4 * c4);
        const int slot = c4 ^ ((ch >> 2) & 3);
        *(float4*)&wsm[ch * WSTR + 4 * slot] = w;
    }
    __syncthreads();

    float acc[4];
    #pragma unroll
    for (int c = 0; c < 4; c++) acc[c] = bvs[4 * cq + c];

    // ---- Prefetch W half 1 (cc 64..127) into registers during pass 0 ----
    float4 rw[8];
    #pragma unroll
    for (int k = 0; k < 8; k++) {
        const int flat = t + NT * k;
        const int ch = flat >> 4, c4 = flat & 15;
        rw[k] = *(const float4*)(Wv + ch * C_CH + 64 + 4 * c4);
    }

    const int sw = cq & 3;   // per-thread W column swizzle

    // ---- Pass 0: cc 0..63 ----
    #pragma unroll
    for (int ck = 0; ck < 16; ck++) {
        const float4 f4 = *(const float4*)&fsm[pt * FSTR + 4 * ck];
        const int sck = 4 * (ck ^ sw);
        #pragma unroll
        for (int c = 0; c < 4; c++) {
            const float4 w = *(const float4*)&wsm[(4 * cq + c) * WSTR + sck];
            acc[c] = fmaf(w.x, f4.x, acc[c]);
            acc[c] = fmaf(w.y, f4.y, acc[c]);
            acc[c] = fmaf(w.z, f4.z, acc[c]);
            acc[c] = fmaf(w.w, f4.w, acc[c]);
        }
    }
    __syncthreads();

    // ---- Store W half 1, then pass 1: cc 64..127 ----
    #pragma unroll
    for (int k = 0; k < 8; k++) {
        const int flat = t + NT * k;
        const int ch = flat >> 4, c4 = flat & 15;
        const int slot = c4 ^ ((ch >> 2) & 3);
        *(float4*)&wsm[ch * WSTR + 4 * slot] = rw[k];
    }
    __syncthreads();

    #pragma unroll
    for (int ck = 0; ck < 16; ck++) {
        const float4 f4 = *(const float4*)&fsm[pt * FSTR + 64 + 4 * ck];
        const int sck = 4 * (ck ^ sw);
        #pragma unroll
        for (int c = 0; c < 4; c++) {
            const float4 w = *(const float4*)&wsm[(4 * cq + c) * WSTR + sck];
            acc[c] = fmaf(w.x, f4.x, acc[c]);
            acc[c] = fmaf(w.y, f4.y, acc[c]);
            acc[c] = fmaf(w.z, f4.z, acc[c]);
            acc[c] = fmaf(w.w, f4.w, acc[c]);
        }
    }

    // ---- Per-(slice, group) partial stats: reduce over 8 pts (width-8) ----
    {
        float s  = acc[0] + acc[1] + acc[2] + acc[3];
        float ss = fmaf(acc[0], acc[0], fmaf(acc[1], acc[1],
                   fmaf(acc[2], acc[2], acc[3] * acc[3])));
        s  += __shfl_down_sync(0xffffffffu, s,  4, 8);
        ss += __shfl_down_sync(0xffffffffu, ss, 4, 8);
        s  += __shfl_down_sync(0xffffffffu, s,  2, 8);
        ss += __shfl_down_sync(0xffffffffu, ss, 2, 8);
        s  += __shfl_down_sync(0xffffffffu, s,  1, 8);
        ss += __shfl_down_sync(0xffffffffu, ss, 1, 8);
        if (pt == 0) {
            float2 p; p.x = s; p.y = ss;
            g_part[b][slice][cq] = p;
            __threadfence();
        }
    }
    __syncthreads();

    // ---- Grid-wide barrier (ticket-based, replay-safe) ----
    if (t == 0) {
        __threadfence();
        const unsigned ticket = atomicAdd(&g_ctr, 1u);
        const unsigned target = (ticket & ~127u) + 128u;
        volatile unsigned* vc = &g_ctr;
        while ((int)(*vc - target) < 0) { }
        __threadfence();
    }
    __syncthreads();

    // ---- Phase 2: combine 64 slice-partials per group (fixed order) ----
    {
        const int g2 = t >> 3;   // group 0..31
        const int i  = t & 7;
        float s2 = 0.f, ss2 = 0.f;
        #pragma unroll
        for (int k = 0; k < 8; k++) {
            const float2 p = g_part[b][i + 8 * k][g2];
            s2  += p.x;
            ss2 += p.y;
        }
        s2  += __shfl_down_sync(0xffffffffu, s2,  4, 8);
        ss2 += __shfl_down_sync(0xffffffffu, ss2, 4, 8);
        s2  += __shfl_down_sync(0xffffffffu, s2,  2, 8);
        ss2 += __shfl_down_sync(0xffffffffu, ss2, 2, 8);
        s2  += __shfl_down_sync(0xffffffffu, s2,  1, 8);
        ss2 += __shfl_down_sync(0xffffffffu, ss2, 1, 8);
        if (i == 0) {
            const float inv_n = 1.0f / 2048.0f;    // 4 ch * 512 pts
            const float m   = s2 * inv_n;
            const float var = ss2 * inv_n - m * m; // biased (jnp.var)
            float2 st; st.x = m; st.y = rsqrtf(var + EPS_GN);
            stat_s[g2] = st;
        }
    }
    __syncthreads();

    // ---- Normalize + ReLU + store (v still in registers) ----
    {
        const float2 st = stat_s[cq];
        #pragma unroll
        for (int c = 0; c < 4; c++) {
            const int ch = 4 * cq + c;
            const float ga = gsm[ch] * st.y;
            const float be = bsm[ch];
            const float y  = fmaxf(fmaf(acc[c] - st.x, ga, be), 0.f);
            out[(size_t)b * C_CH * NPT + ch * NPT + p0 + pt] = y;
        }
    }
}

extern "C" void kernel_launch(void* const* d_in, const int* in_sizes, int n_in,
                              void* d_out, int out_size) {
    // metadata order:
    // 0 feat, 1 Wk, 2 bk, 3 Wq, 4 bq, 5 Wv, 6 bv, 7 gn_v_g, 8 gn_v_b,
    // 9 gn1_g, 10 gn1_b, 11 W1, 12 b1, 13 gn2_g, 14 gn2_b, 15 W2, 16 b2
    const float* feat = (const float*)d_in[0];
    const float* Wv   = (const float*)d_in[5];
    const float* bv   = (const float*)d_in[6];
    const float* gn_g = (const float*)d_in[7];
    const float* gn_b = (const float*)d_in[8];
    float* out = (float*)d_out;

    (void)in_sizes; (void)n_in; (void)out_size;

    fused_v_gn_relu_kernel<<<128, NT>>>(feat, Wv, bv, gn_g, gn_b, out);
}

// round 12
// speedup vs baseline: 1.2330x; 1.2330x over previous
#include <cuda_runtime.h>

// out = relu( GroupNorm32( Wv @ feat + bv, gn_v_g, gn_v_b ) )
// (softmax-weighted sum in the reference is identity: v is constant along the
//  softmax axis and softmax rows sum to 1).
//
// feat [2,128,512], Wv [128,128], out [2,128,512].
// Grid: 64 blocks = B(2) x group(32); one CTA owns a full GN group.
// 512 threads: tx = 128 float4 columns, ty = 4 cc-quarters.
// Thread: 32 cc x 4 pts x 4 ch = 512 FMA-inst, 32 LDG.128 double-buffered.
// R11 trims vs R8: bv folded in AFTER the mainloop (acc starts at 0, bv is a
// per-channel constant), gamma/beta/bv fetched into registers right after the
// mainloop so their latency hides under the reduction, no param smem staging.

#define C_CH     128
#define NPT      512
#define CH_PER_G 4
#define EPS_GN   1e-5f
#define NTHREADS 512
#define ROW4     (NPT / 4)     // 128 float4 per feat row
#define CC_PER_T (C_CH / 4)    // 32 cc per ty
#define CHUNK    8
#define NWARPS   (NTHREADS / 32)

__device__ __forceinline__ float4 f4add(float4 a, float4 b) {
    a.x += b.x; a.y += b.y; a.z += b.z; a.w += b.w; return a;
}

__global__ __launch_bounds__(NTHREADS, 1)
void fused_v_gn_relu_kernel(const float* __restrict__ feat,
                            const float* __restrict__ Wv,
                            const float* __restrict__ bv,
                            const float* __restrict__ gamma,
                            const float* __restrict__ beta,
                            float* __restrict__ out) {
    const int g  = blockIdx.x & 31;   // group 0..31
    const int b  = blockIdx.x >> 5;   // batch 0..1
    const int c0 = g * CH_PER_G;
    const int t  = threadIdx.x;       // 0..511
    const int tx = t & 127;           // float4 column (0..127)
    const int ty = t >> 7;            // cc quarter (0..3)

    __shared__ float  wt_s[C_CH * CH_PER_G];          // transposed Wv, 2KB
    __shared__ float4 part_s[4 * CH_PER_G * ROW4];    // [ty][c][col], 32KB
    __shared__ float2 red_s[NWARPS];                  // warp {sum, sumsq}

    // Stage Wv transposed (one element per thread):
    // wt_s[cc*4 + c] = Wv[(c0+c)*128 + cc].
    wt_s[t] = Wv[(c0 + (t & 3)) * C_CH + (t >> 2)];

    // feat as float4 rows; this thread's column within its cc quarter.
    const float4* fp = (const float4*)(feat + (size_t)b * C_CH * NPT)
                       + (size_t)(ty * CC_PER_T) * ROW4 + tx;

    // Prime the double buffer before the sync (LDG latency overlaps staging).
    float4 cur[CHUNK], nxt[CHUNK];
    #pragma unroll
    for (int i = 0; i < CHUNK; i++) cur[i] = fp[i * ROW4];

    __syncthreads();

    const float4* wt4 = (const float4*)wt_s;
    const int wbase = ty * CC_PER_T;

    float4 acc[CH_PER_G];
    #pragma unroll
    for (int c = 0; c < CH_PER_G; c++) {
        acc[c].x = 0.f; acc[c].y = 0.f; acc[c].z = 0.f; acc[c].w = 0.f;
    }

    // Double-buffered mainloop: 4 chunks of (8 LDG.128 + 128 FMA-inst).
    #pragma unroll
    for (int cb = 0; cb < CC_PER_T; cb += CHUNK) {
        if (cb + CHUNK < CC_PER_T) {
            #pragma unroll
            for (int i = 0; i < CHUNK; i++)
                nxt[i] = fp[(cb + CHUNK + i) * ROW4];
        }
        #pragma unroll
        for (int i = 0; i < CHUNK; i++) {
            const float4 w = wt4[wbase + cb + i];   // broadcast LDS.128
            const float4 f = cur[i];
            acc[0].x = fmaf(w.x, f.x, acc[0].x);
            acc[0].y = fmaf(w.x, f.y, acc[0].y);
            acc[0].z = fmaf(w.x, f.z, acc[0].z);
            acc[0].w = fmaf(w.x, f.w, acc[0].w);
            acc[1].x = fmaf(w.y, f.x, acc[1].x);
            acc[1].y = fmaf(w.y, f.y, acc[1].y);
            acc[1].z = fmaf(w.y, f.z, acc[1].z);
            acc[1].w = fmaf(w.y, f.w, acc[1].w);
            acc[2].x = fmaf(w.z, f.x, acc[2].x);
            acc[2].y = fmaf(w.z, f.y, acc[2].y);
            acc[2].z = fmaf(w.z, f.z, acc[2].z);
            acc[2].w = fmaf(w.z, f.w, acc[2].w);
            acc[3].x = fmaf(w.w, f.x, acc[3].x);
            acc[3].y = fmaf(w.w, f.y, acc[3].y);
            acc[3].z = fmaf(w.w, f.z, acc[3].z);
            acc[3].w = fmaf(w.w, f.w, acc[3].w);
        }
        #pragma unroll
        for (int i = 0; i < CHUNK; i++) cur[i] = nxt[i];
    }

    // Fetch this thread's per-channel params NOW: latency hides under the
    // STS + sync + fold below.  Thread t owns channel c0 + (t>>7) after fold.
    const int   myc = c0 + (t >> 7);
    const float bvc = bv[myc];
    const float gac = gamma[myc];
    const float bec = beta[myc];

    // Publish cc-quarter partials: part_s[ty*512 + c*128 + col].
    #pragma unroll
    for (int c = 0; c < CH_PER_G; c++)
        part_s[ty * 512 + c * ROW4 + tx] = acc[c];
    __syncthreads();

    // Fold 4 partials (thread t owns flat [c][col] index t) and add bv.
    float4 v = f4add(f4add(part_s[t], part_s[t + 512]),
                     f4add(part_s[t + 1024], part_s[t + 1536]));
    v.x += bvc; v.y += bvc; v.z += bvc; v.w += bvc;

    // Block GN stats: warp shfl -> 16 warp partials -> redundant sum.
    {
        float ps  = v.x + v.y + v.z + v.w;
        float pss = fmaf(v.x, v.x, fmaf(v.y, v.y,
                    fmaf(v.z, v.z, v.w * v.w)));
        #pragma unroll
        for (int off = 16; off > 0; off >>= 1) {
            ps  += __shfl_xor_sync(0xffffffffu, ps,  off);
            pss += __shfl_xor_sync(0xffffffffu, pss, off);
        }
        const int lane = t & 31, wid = t >> 5;
        if (lane == 0) {
            float2 p; p.x = ps; p.y = pss;
            red_s[wid] = p;
        }
    }
    __syncthreads();

    // Every thread sums the 16 warp partials redundantly (fixed order).
    float ts = 0.f, tss = 0.f;
    #pragma unroll
    for (int w = 0; w < NWARPS; w++) {
        const float2 p = red_s[w];
        ts  += p.x;
        tss += p.y;
    }
    const float inv_n = 1.0f / (float)(CH_PER_G * NPT);
    const float m     = ts * inv_n;
    const float var   = tss * inv_n - m * m;   // biased (jnp.var)
    const float rst   = rsqrtf(var + EPS_GN);

    // Normalize + ReLU + store: one STG.128 per thread.
    {
        const float ga = gac * rst;
        float4 y;
        y.x = fmaxf(fmaf(v.x - m, ga, bec), 0.f);
        y.y = fmaxf(fmaf(v.y - m, ga, bec), 0.f);
        y.z = fmaxf(fmaf(v.z - m, ga, bec), 0.f);
        y.w = fmaxf(fmaf(v.w - m, ga, bec), 0.f);
        float4* ob = (float4*)(out + (size_t)b * C_CH * NPT);
        ob[(size_t)myc * ROW4 + (t & 127)] = y;
    }
}

extern "C" void kernel_launch(void* const* d_in, const int* in_sizes, int n_in,
                              void* d_out, int out_size) {
    // metadata order:
    // 0 feat, 1 Wk, 2 bk, 3 Wq, 4 bq, 5 Wv, 6 bv, 7 gn_v_g, 8 gn_v_b,
    // 9 gn1_g, 10 gn1_b, 11 W1, 12 b1, 13 gn2_g, 14 gn2_b, 15 W2, 16 b2
    const float* feat = (const float*)d_in[0];
    const float* Wv   = (const float*)d_in[5];
    const float* bv   = (const float*)d_in[6];
    const float* gn_g = (const float*)d_in[7];
    const float* gn_b = (const float*)d_in[8];
    float* out = (float*)d_out;

    (void)in_sizes; (void)n_in; (void)out_size;

    fused_v_gn_relu_kernel<<<64, NTHREADS>>>(feat, Wv, bv, gn_g, gn_b, out);
}

// round 13
// speedup vs baseline: 1.2694x; 1.0295x over previous
#include <cuda_runtime.h>

// out = relu( GroupNorm32( Wv @ feat + bv, gn_v_g, gn_v_b ) )
// (softmax-weighted sum in the reference is identity: v is constant along the
//  softmax axis and softmax rows sum to 1).
//
// feat [2,128,512], Wv [128,128], out [2,128,512].
// Grid: 64 blocks = B(2) x group(32); one CTA owns a full GN group.
// 512 threads: tx = 128 float4 columns, ty = 4 cc-quarters.
// R12 vs R11: mainloop re-pipelined, CHUNK 8->4 with a 4-slot rotating buffer
// prefetching THREE chunks ahead (distance ~1536 cyc of SMSP FFMA issue vs
// ~900 cyc effective L1tex-queue + L2 latency) -- same 64 buffer registers as
// the old double buffer, smoother 4-LDG bursts (lower L1tex queue peaks).

#define C_CH     128
#define NPT      512
#define CH_PER_G 4
#define EPS_GN   1e-5f
#define NTHREADS 512
#define ROW4     (NPT / 4)     // 128 float4 per feat row
#define CC_PER_T (C_CH / 4)    // 32 cc per ty
#define CHUNK    4
#define NCHUNK   (CC_PER_T / CHUNK)   // 8 chunks per thread
#define NBUF     4                    // rotating buffer slots
#define NWARPS   (NTHREADS / 32)

__device__ __forceinline__ float4 f4add(float4 a, float4 b) {
    a.x += b.x; a.y += b.y; a.z += b.z; a.w += b.w; return a;
}

__global__ __launch_bounds__(NTHREADS, 1)
void fused_v_gn_relu_kernel(const float* __restrict__ feat,
                            const float* __restrict__ Wv,
                            const float* __restrict__ bv,
                            const float* __restrict__ gamma,
                            const float* __restrict__ beta,
                            float* __restrict__ out) {
    const int g  = blockIdx.x & 31;   // group 0..31
    const int b  = blockIdx.x >> 5;   // batch 0..1
    const int c0 = g * CH_PER_G;
    const int t  = threadIdx.x;       // 0..511
    const int tx = t & 127;           // float4 column (0..127)
    const int ty = t >> 7;            // cc quarter (0..3)

    __shared__ float  wt_s[C_CH * CH_PER_G];          // transposed Wv, 2KB
    __shared__ float4 part_s[4 * CH_PER_G * ROW4];    // [ty][c][col], 32KB
    __shared__ float2 red_s[NWARPS];                  // warp {sum, sumsq}

    // Stage Wv transposed (one element per thread):
    // wt_s[cc*4 + c] = Wv[(c0+c)*128 + cc].
    wt_s[t] = Wv[(c0 + (t & 3)) * C_CH + (t >> 2)];

    // feat as float4 rows; this thread's column within its cc quarter.
    const float4* fp = (const float4*)(feat + (size_t)b * C_CH * NPT)
                       + (size_t)(ty * CC_PER_T) * ROW4 + tx;

    // Prime 3 chunks (12 LDG.128) before the sync.
    float4 buf[NBUF][CHUNK];
    #pragma unroll
    for (int k = 0; k < 3; k++)
        #pragma unroll
        for (int i = 0; i < CHUNK; i++)
            buf[k][i] = fp[(k * CHUNK + i) * ROW4];

    __syncthreads();

    const float4* wt4 = (const float4*)wt_s;
    const int wbase = ty * CC_PER_T;

    float4 acc[CH_PER_G];
    #pragma unroll
    for (int c = 0; c < CH_PER_G; c++) {
        acc[c].x = 0.f; acc[c].y = 0.f; acc[c].z = 0.f; acc[c].w = 0.f;
    }

    // Rotating-buffer mainloop: prefetch chunk k+3 while computing chunk k.
    #pragma unroll
    for (int k = 0; k < NCHUNK; k++) {
        if (k + 3 < NCHUNK) {
            #pragma unroll
            for (int i = 0; i < CHUNK; i++)
                buf[(k + 3) & (NBUF - 1)][i] = fp[((k + 3) * CHUNK + i) * ROW4];
        }
        #pragma unroll
        for (int i = 0; i < CHUNK; i++) {
            const float4 w = wt4[wbase + k * CHUNK + i];   // broadcast LDS.128
            const float4 f = buf[k & (NBUF - 1)][i];
            acc[0].x = fmaf(w.x, f.x, acc[0].x);
            acc[0].y = fmaf(w.x, f.y, acc[0].y);
            acc[0].z = fmaf(w.x, f.z, acc[0].z);
            acc[0].w = fmaf(w.x, f.w, acc[0].w);
            acc[1].x = fmaf(w.y, f.x, acc[1].x);
            acc[1].y = fmaf(w.y, f.y, acc[1].y);
            acc[1].z = fmaf(w.y, f.z, acc[1].z);
            acc[1].w = fmaf(w.y, f.w, acc[1].w);
            acc[2].x = fmaf(w.z, f.x, acc[2].x);
            acc[2].y = fmaf(w.z, f.y, acc[2].y);
            acc[2].z = fmaf(w.z, f.z, acc[2].z);
            acc[2].w = fmaf(w.z, f.w, acc[2].w);
            acc[3].x = fmaf(w.w, f.x, acc[3].x);
            acc[3].y = fmaf(w.w, f.y, acc[3].y);
            acc[3].z = fmaf(w.w, f.z, acc[3].z);
            acc[3].w = fmaf(w.w, f.w, acc[3].w);
        }
    }

    // Fetch per-channel params now: latency hides under the reduction tail.
    const int   myc = c0 + (t >> 7);
    const float bvc = bv[myc];
    const float gac = gamma[myc];
    const float bec = beta[myc];

    // Publish cc-quarter partials: part_s[ty*512 + c*128 + col].
    #pragma unroll
    for (int c = 0; c < CH_PER_G; c++)
        part_s[ty * 512 + c * ROW4 + tx] = acc[c];
    __syncthreads();

    // Fold 4 partials (thread t owns flat [c][col] index t) and add bv.
    float4 v = f4add(f4add(part_s[t], part_s[t + 512]),
                     f4add(part_s[t + 1024], part_s[t + 1536]));
    v.x += bvc; v.y += bvc; v.z += bvc; v.w += bvc;

    // Block GN stats: warp shfl -> 16 warp partials -> redundant sum.
    {
        float ps  = v.x + v.y + v.z + v.w;
        float pss = fmaf(v.x, v.x, fmaf(v.y, v.y,
                    fmaf(v.z, v.z, v.w * v.w)));
        #pragma unroll
        for (int off = 16; off > 0; off >>= 1) {
            ps  += __shfl_xor_sync(0xffffffffu, ps,  off);
            pss += __shfl_xor_sync(0xffffffffu, pss, off);
        }
        const int lane = t & 31, wid = t >> 5;
        if (lane == 0) {
            float2 p; p.x = ps; p.y = pss;
            red_s[wid] = p;
        }
    }
    __syncthreads();

    // Every thread sums the 16 warp partials redundantly (fixed order).
    float ts = 0.f, tss = 0.f;
    #pragma unroll
    for (int w = 0; w < NWARPS; w++) {
        const float2 p = red_s[w];
        ts  += p.x;
        tss += p.y;
    }
    const float inv_n = 1.0f / (float)(CH_PER_G * NPT);
    const float m     = ts * inv_n;
    const float var   = tss * inv_n - m * m;   // biased (jnp.var)
    const float rst   = rsqrtf(var + EPS_GN);

    // Normalize + ReLU + store: one STG.128 per thread.
    {
        const float ga = gac * rst;
        float4 y;
        y.x = fmaxf(fmaf(v.x - m, ga, bec), 0.f);
        y.y = fmaxf(fmaf(v.y - m, ga, bec), 0.f);
        y.z = fmaxf(fmaf(v.z - m, ga, bec), 0.f);
        y.w = fmaxf(fmaf(v.w - m, ga, bec), 0.f);
        float4* ob = (float4*)(out + (size_t)b * C_CH * NPT);
        ob[(size_t)myc * ROW4 + (t & 127)] = y;
    }
}

extern "C" void kernel_launch(void* const* d_in, const int* in_sizes, int n_in,
                              void* d_out, int out_size) {
    // metadata order:
    // 0 feat, 1 Wk, 2 bk, 3 Wq, 4 bq, 5 Wv, 6 bv, 7 gn_v_g, 8 gn_v_b,
    // 9 gn1_g, 10 gn1_b, 11 W1, 12 b1, 13 gn2_g, 14 gn2_b, 15 W2, 16 b2
    const float* feat = (const float*)d_in[0];
    const float* Wv   = (const float*)d_in[5];
    const float* bv   = (const float*)d_in[6];
    const float* gn_g = (const float*)d_in[7];
    const float* gn_b = (const float*)d_in[8];
    float* out = (float*)d_out;

    (void)in_sizes; (void)n_in; (void)out_size;

    fused_v_gn_relu_kernel<<<64, NTHREADS>>>(feat, Wv, bv, gn_g, gn_b, out);
}